// round 4
// baseline (speedup 1.0000x reference)
#include <cuda_runtime.h>
#include <cstdint>
#include <cstddef>

// Problem constants
#define S_LEN 2048
#define I_DIM 4096
#define O_DIM 4096
#define M_DIM 8192            // B*S
#define NGRP  32              // I / 128 groups

// ---------------------------------------------------------------------------
// Scratch (device globals)
// ---------------------------------------------------------------------------
__device__ __align__(16) signed char g_qx[(size_t)M_DIM * I_DIM];  // quantized acts [m][i]
__device__ __align__(16) signed char g_ws[(size_t)O_DIM * I_DIM];  // w_int - zero   [o][i]

// ---------------------------------------------------------------------------
// Fused prep kernel.
//   blocks [0, 8192)        : unpack int4 weights -> int8 (one thread per int4)
//   blocks [8192, 40960)    : quantize activations (one thread per float4)
// ---------------------------------------------------------------------------
__global__ void prep_kernel(const float* __restrict__ x,
                            const float* __restrict__ act_scale,
                            const int* __restrict__ qweight,
                            const int* __restrict__ weight_zero) {
    if (blockIdx.x < 8192) {
        int idx = blockIdx.x * 256 + threadIdx.x;             // 0 .. O*I/8-1
        int o = idx >> 9;                                     // 512 int4 per row
        int j4 = idx & 511;
        int grp = j4 >> 4;                                    // 16 int4 per group
        int z = weight_zero[o * NGRP + grp];
        int4 v = reinterpret_cast<const int4*>(qweight)[idx];
        signed char w[8];
        w[0] = (signed char)((v.x & 15) - z);  w[1] = (signed char)(((v.x >> 4) & 15) - z);
        w[2] = (signed char)((v.y & 15) - z);  w[3] = (signed char)(((v.y >> 4) & 15) - z);
        w[4] = (signed char)((v.z & 15) - z);  w[5] = (signed char)(((v.z >> 4) & 15) - z);
        w[6] = (signed char)((v.w & 15) - z);  w[7] = (signed char)(((v.w >> 4) & 15) - z);
        reinterpret_cast<uint2*>(g_ws)[idx] = *reinterpret_cast<uint2*>(w);
    } else {
        int idx = (blockIdx.x - 8192) * 256 + threadIdx.x;    // float4 index
        float4 v = reinterpret_cast<const float4*>(x)[idx];
        int m = idx >> 10;                                    // 1024 float4 per row
        float s = act_scale[m & (S_LEN - 1)];

        float r0 = rintf(__fdiv_rn(v.x, s));
        float r1 = rintf(__fdiv_rn(v.y, s));
        float r2 = rintf(__fdiv_rn(v.z, s));
        float r3 = rintf(__fdiv_rn(v.w, s));
        r0 = fmaxf(-127.f, fminf(127.f, r0));
        r1 = fmaxf(-127.f, fminf(127.f, r1));
        r2 = fmaxf(-127.f, fminf(127.f, r2));
        r3 = fmaxf(-127.f, fminf(127.f, r3));

        char4 q;
        q.x = (signed char)(int)r0;
        q.y = (signed char)(int)r1;
        q.z = (signed char)(int)r2;
        q.w = (signed char)(int)r3;
        reinterpret_cast<char4*>(g_qx)[idx] = q;
    }
}

// ---------------------------------------------------------------------------
// GEMM helpers
// ---------------------------------------------------------------------------
__device__ __forceinline__ void cp16(unsigned smem_dst, const void* gmem_src) {
    asm volatile("cp.async.cg.shared.global [%0], [%1], 16;\n" :: "r"(smem_dst), "l"(gmem_src));
}

__device__ __forceinline__ void ldsm4(unsigned& r0, unsigned& r1, unsigned& r2,
                                      unsigned& r3, unsigned addr) {
    asm volatile("ldmatrix.sync.aligned.m8n8.x4.shared.b16 {%0,%1,%2,%3}, [%4];"
                 : "=r"(r0), "=r"(r1), "=r"(r2), "=r"(r3) : "r"(addr));
}

__device__ __forceinline__ void mma_s8(int* c, const unsigned* a, const unsigned* b) {
    asm volatile(
        "mma.sync.aligned.m16n8k32.row.col.s32.s8.s8.s32 "
        "{%0,%1,%2,%3},{%4,%5,%6,%7},{%8,%9},{%0,%1,%2,%3};\n"
        : "+r"(c[0]), "+r"(c[1]), "+r"(c[2]), "+r"(c[3])
        : "r"(a[0]), "r"(a[1]), "r"(a[2]), "r"(a[3]), "r"(b[0]), "r"(b[1]));
}

// ---------------------------------------------------------------------------
// GEMM: CTA 128x128, K-slab 256 (2 groups / stage), 512 threads (16 warps 4x4).
//   SMEM rows 256B wide = two independent 128B swizzle blocks.
//   2-stage cp.async pipeline; per-group exact int32 rescale in fp32.
// SMEM: A stage 32KB + B stage 32KB, x2 stages = 128KB, + 16KB wscale = 145KB
// ---------------------------------------------------------------------------
#define ROWB       256
#define STAGE_A    (128 * ROWB)               // 32768
#define STAGE_AB   (2 * STAGE_A)              // 65536 (A+B one stage)
#define SMEM_SCALE (2 * STAGE_AB)             // 131072
#define SMEM_TOTAL (SMEM_SCALE + 16384)       // 147456

#define NSLAB 16                              // 4096 / 256

__global__ __launch_bounds__(512, 1)
void gemm_kernel(const float* __restrict__ act_scale,
                 const float* __restrict__ wscale,     // (O, 32)
                 const float* __restrict__ bias,
                 float* __restrict__ out) {
    extern __shared__ char smem[];
    const unsigned smem_base = (unsigned)__cvta_generic_to_shared(smem);

    const int bn = blockIdx.x;              // 0..31
    const int bm = blockIdx.y;              // 0..63
    const int tid = threadIdx.x;
    const int lane = tid & 31;
    const int wid = tid >> 5;
    const int wm = wid >> 2;                // 0..3 (M)
    const int wn = wid & 3;                 // 0..3 (N)

    const signed char* gA = g_qx + (size_t)bm * 128 * I_DIM;
    const signed char* gB = g_ws + (size_t)bn * 128 * I_DIM;

    // stage wscale for this CTA's 128 cols: sScale[c*32+g]
    float* sScale = reinterpret_cast<float*>(smem + SMEM_SCALE);
    {
        const float4* src = reinterpret_cast<const float4*>(wscale + (size_t)bn * 128 * NGRP);
        float4* dst = reinterpret_cast<float4*>(sScale);
        dst[tid] = src[tid];
        dst[tid + 512] = src[tid + 512];
    }

    // --- slab loader: 256 K-bytes (2 groups) of A and B ---
    auto load_slab = [&](int s, int buf) {
        unsigned dA = smem_base + buf * STAGE_AB;
        unsigned dB = dA + STAGE_A;
        const char* sAg = reinterpret_cast<const char*>(gA) + s * ROWB;
        const char* sBg = reinterpret_cast<const char*>(gB) + s * ROWB;
#pragma unroll
        for (int it = 0; it < 4; ++it) {
            int c = tid + it * 512;         // 0..2047
            int row = c >> 4, unit = c & 15;
            int b128 = unit >> 3, u7 = unit & 7;
            unsigned off = row * ROWB + b128 * 128 + ((u7 ^ (row & 7)) << 4);
            cp16(dA + off, sAg + (size_t)row * I_DIM + unit * 16);
            cp16(dB + off, sBg + (size_t)row * I_DIM + unit * 16);
        }
    };

    load_slab(0, 0);
    asm volatile("cp.async.commit_group;\n");

    // per-lane ldmatrix address components
    const int selA_row = ((lane >> 3) & 1) * 8 + (lane & 7);
    const int bhA = lane >> 4;              // 0/1 : 16B half of k32
    const int selB_row = ((lane >> 4) & 1) * 8 + (lane & 7);
    const int bhB = (lane >> 3) & 1;

    float acc_f[2][4][4];
#pragma unroll
    for (int i = 0; i < 2; ++i)
#pragma unroll
        for (int j = 0; j < 4; ++j)
#pragma unroll
            for (int k = 0; k < 4; ++k) acc_f[i][j][k] = 0.f;

    __syncthreads();                        // sScale visible

    for (int s = 0; s < NSLAB; ++s) {
        if (s + 1 < NSLAB) {
            load_slab(s + 1, (s + 1) & 1);
            asm volatile("cp.async.commit_group;\n");
            asm volatile("cp.async.wait_group 1;\n");
        } else {
            asm volatile("cp.async.wait_group 0;\n");
        }
        __syncthreads();                    // slab s visible

        const unsigned aBase = smem_base + (s & 1) * STAGE_AB;
        const unsigned bBase = aBase + STAGE_A;

#pragma unroll
        for (int h = 0; h < 2; ++h) {       // two groups in this slab
            const int g = 2 * s + h;

            int acc_i[2][4][4];
#pragma unroll
            for (int i = 0; i < 2; ++i)
#pragma unroll
                for (int j = 0; j < 4; ++j)
#pragma unroll
                    for (int k = 0; k < 4; ++k) acc_i[i][j][k] = 0;

#pragma unroll
            for (int kk = 0; kk < 4; ++kk) {
                unsigned a[2][4];
                unsigned b[4][2];
#pragma unroll
                for (int mt = 0; mt < 2; ++mt) {
                    int row = wm * 32 + mt * 16 + selA_row;
                    unsigned slot = (unsigned)((kk * 2 + bhA) ^ (row & 7));
                    ldsm4(a[mt][0], a[mt][1], a[mt][2], a[mt][3],
                          aBase + row * ROWB + h * 128 + (slot << 4));
                }
#pragma unroll
                for (int p = 0; p < 2; ++p) {
                    int row = wn * 32 + p * 16 + selB_row;
                    unsigned slot = (unsigned)((kk * 2 + bhB) ^ (row & 7));
                    ldsm4(b[2 * p][0], b[2 * p][1], b[2 * p + 1][0], b[2 * p + 1][1],
                          bBase + row * ROWB + h * 128 + (slot << 4));
                }
#pragma unroll
                for (int mt = 0; mt < 2; ++mt)
#pragma unroll
                    for (int nt = 0; nt < 4; ++nt)
                        mma_s8(acc_i[mt][nt], a[mt], b[nt]);
            }

            // fold exact int32 group sums with per-(col,group) scale
#pragma unroll
            for (int nt = 0; nt < 4; ++nt) {
                int c0 = wn * 32 + nt * 8 + 2 * (lane & 3);
                float s0 = sScale[c0 * NGRP + g];
                float s1 = sScale[(c0 + 1) * NGRP + g];
#pragma unroll
                for (int mt = 0; mt < 2; ++mt) {
                    acc_f[mt][nt][0] += s0 * (float)acc_i[mt][nt][0];
                    acc_f[mt][nt][1] += s1 * (float)acc_i[mt][nt][1];
                    acc_f[mt][nt][2] += s0 * (float)acc_i[mt][nt][2];
                    acc_f[mt][nt][3] += s1 * (float)acc_i[mt][nt][3];
                }
            }
        }
        __syncthreads();                    // stage reusable
    }

    // --- epilogue: out = s_act[m] * acc + bias[o] ---
#pragma unroll
    for (int mt = 0; mt < 2; ++mt) {
        int r0 = bm * 128 + wm * 32 + mt * 16 + (lane >> 2);
        float sa0 = __ldg(act_scale + (r0 & (S_LEN - 1)));
        float sa1 = __ldg(act_scale + ((r0 + 8) & (S_LEN - 1)));
#pragma unroll
        for (int nt = 0; nt < 4; ++nt) {
            int c0 = bn * 128 + wn * 32 + nt * 8 + 2 * (lane & 3);
            float b0 = __ldg(bias + c0);
            float b1 = __ldg(bias + c0 + 1);
            float2 v0, v1;
            v0.x = sa0 * acc_f[mt][nt][0] + b0;
            v0.y = sa0 * acc_f[mt][nt][1] + b1;
            v1.x = sa1 * acc_f[mt][nt][2] + b0;
            v1.y = sa1 * acc_f[mt][nt][3] + b1;
            *reinterpret_cast<float2*>(&out[(size_t)r0 * O_DIM + c0]) = v0;
            *reinterpret_cast<float2*>(&out[(size_t)(r0 + 8) * O_DIM + c0]) = v1;
        }
    }
}

// ---------------------------------------------------------------------------
// Launch. Inputs: x, qweight, act_scale, weight_scale, weight_zero, bias.
// ---------------------------------------------------------------------------
extern "C" void kernel_launch(void* const* d_in, const int* in_sizes, int n_in,
                              void* d_out, int out_size) {
    const float* x        = (const float*)d_in[0];
    const int*   qweight  = (const int*)d_in[1];
    const float* actscale = (const float*)d_in[2];
    const float* wscale   = (const float*)d_in[3];
    const int*   wzero    = (const int*)d_in[4];
    const float* bias     = (const float*)d_in[5];
    float* out = (float*)d_out;

    prep_kernel<<<40960, 256>>>(x, actscale, qweight, wzero);

    cudaFuncSetAttribute(gemm_kernel,
                         cudaFuncAttributeMaxDynamicSharedMemorySize, SMEM_TOTAL);
    dim3 grid(O_DIM / 128, M_DIM / 128);   // (32, 64); bn fastest for B-tile L2 reuse
    gemm_kernel<<<grid, 512, SMEM_TOTAL>>>(actscale, wscale, bias, out);
}

// round 6
// speedup vs baseline: 1.0986x; 1.0986x over previous
#include <cuda_runtime.h>
#include <cstdint>
#include <cstddef>

// Problem constants
#define S_LEN 2048
#define I_DIM 4096
#define O_DIM 4096
#define M_DIM 8192            // B*S
#define NGRP  32              // I / 128 groups

// ---------------------------------------------------------------------------
// Scratch (device globals)
// ---------------------------------------------------------------------------
__device__ __align__(16) signed char g_qx[(size_t)M_DIM * I_DIM];  // quantized acts [m][i]
__device__ __align__(16) signed char g_ws[(size_t)O_DIM * I_DIM];  // w_int - zero   [o][i]

// ---------------------------------------------------------------------------
// Fused prep kernel.
//   blocks [0, 8192)     : unpack int4 weights -> int8 (one thread per int4)
//   blocks [8192, 40960) : quantize activations (one thread per float4)
// ---------------------------------------------------------------------------
__global__ void prep_kernel(const float* __restrict__ x,
                            const float* __restrict__ act_scale,
                            const int* __restrict__ qweight,
                            const int* __restrict__ weight_zero) {
    if (blockIdx.x < 8192) {
        int idx = blockIdx.x * 256 + threadIdx.x;             // 0 .. O*I/8-1
        int o = idx >> 9;                                     // 512 int4 per row
        int j4 = idx & 511;
        int grp = j4 >> 4;                                    // 16 int4 per group
        int z = weight_zero[o * NGRP + grp];
        int4 v = reinterpret_cast<const int4*>(qweight)[idx];
        signed char w[8];
        w[0] = (signed char)((v.x & 15) - z);  w[1] = (signed char)(((v.x >> 4) & 15) - z);
        w[2] = (signed char)((v.y & 15) - z);  w[3] = (signed char)(((v.y >> 4) & 15) - z);
        w[4] = (signed char)((v.z & 15) - z);  w[5] = (signed char)(((v.z >> 4) & 15) - z);
        w[6] = (signed char)((v.w & 15) - z);  w[7] = (signed char)(((v.w >> 4) & 15) - z);
        reinterpret_cast<uint2*>(g_ws)[idx] = *reinterpret_cast<uint2*>(w);
    } else {
        int idx = (blockIdx.x - 8192) * 256 + threadIdx.x;    // float4 index
        float4 v = reinterpret_cast<const float4*>(x)[idx];
        int m = idx >> 10;                                    // 1024 float4 per row
        float s = act_scale[m & (S_LEN - 1)];

        float r0 = rintf(__fdiv_rn(v.x, s));
        float r1 = rintf(__fdiv_rn(v.y, s));
        float r2 = rintf(__fdiv_rn(v.z, s));
        float r3 = rintf(__fdiv_rn(v.w, s));
        r0 = fmaxf(-127.f, fminf(127.f, r0));
        r1 = fmaxf(-127.f, fminf(127.f, r1));
        r2 = fmaxf(-127.f, fminf(127.f, r2));
        r3 = fmaxf(-127.f, fminf(127.f, r3));

        char4 q;
        q.x = (signed char)(int)r0;
        q.y = (signed char)(int)r1;
        q.z = (signed char)(int)r2;
        q.w = (signed char)(int)r3;
        reinterpret_cast<char4*>(g_qx)[idx] = q;
    }
}

// ---------------------------------------------------------------------------
// GEMM helpers
// ---------------------------------------------------------------------------
__device__ __forceinline__ void cp16(unsigned smem_dst, const void* gmem_src) {
    asm volatile("cp.async.cg.shared.global [%0], [%1], 16;\n" :: "r"(smem_dst), "l"(gmem_src));
}

__device__ __forceinline__ void ldsm4(unsigned& r0, unsigned& r1, unsigned& r2,
                                      unsigned& r3, unsigned addr) {
    asm volatile("ldmatrix.sync.aligned.m8n8.x4.shared.b16 {%0,%1,%2,%3}, [%4];"
                 : "=r"(r0), "=r"(r1), "=r"(r2), "=r"(r3) : "r"(addr));
}

__device__ __forceinline__ void mma_s8(int* c, const unsigned* a, const unsigned* b) {
    asm volatile(
        "mma.sync.aligned.m16n8k32.row.col.s32.s8.s8.s32 "
        "{%0,%1,%2,%3},{%4,%5,%6,%7},{%8,%9},{%0,%1,%2,%3};\n"
        : "+r"(c[0]), "+r"(c[1]), "+r"(c[2]), "+r"(c[3])
        : "r"(a[0]), "r"(a[1]), "r"(a[2]), "r"(a[3]), "r"(b[0]), "r"(b[1]));
}

// ---------------------------------------------------------------------------
// GEMM: CTA 128x128, K-slab 128 (one group), 256 threads = 8 warps (2M x 4N),
//       warp tile 64x32 (mt=4, nt=4) -> ldsm/mma = 0.375.
//   SMEM: 128B rows, XOR-16B swizzle; 3-stage cp.async pipeline.
//   Per-group exact int32 accumulate, fp32 rescale from SMEM-staged wscale.
// SMEM: 3 x 32KB stages + 16KB wscale = 112KB
// ---------------------------------------------------------------------------
#define STAGE_A   16384
#define STAGE_AB  32768
#define SMEM_SCALE (3 * STAGE_AB)             // 98304
#define SMEM_TOTAL (SMEM_SCALE + 16384)       // 114688

__global__ __launch_bounds__(256, 1)
void gemm_kernel(const float* __restrict__ act_scale,
                 const float* __restrict__ wscale,     // (O, 32)
                 const float* __restrict__ bias,
                 float* __restrict__ out) {
    extern __shared__ char smem[];
    const unsigned smem_base = (unsigned)__cvta_generic_to_shared(smem);

    const int bn = blockIdx.x;              // 0..31
    const int bm = blockIdx.y;              // 0..63
    const int tid = threadIdx.x;
    const int lane = tid & 31;
    const int wid = tid >> 5;
    const int wm = wid >> 2;                // 0..1 (M: 64 rows each)
    const int wn = wid & 3;                 // 0..3 (N: 32 cols each)

    const signed char* gA = g_qx + (size_t)bm * 128 * I_DIM;
    const signed char* gB = g_ws + (size_t)bn * 128 * I_DIM;

    // stage wscale for this CTA's 128 cols: sScale[c*32+g]
    float* sScale = reinterpret_cast<float*>(smem + SMEM_SCALE);
    {
        const float4* src = reinterpret_cast<const float4*>(wscale + (size_t)bn * 128 * NGRP);
        float4* dst = reinterpret_cast<float4*>(sScale);
#pragma unroll
        for (int k = 0; k < 4; ++k) dst[tid + k * 256] = src[tid + k * 256];
    }

    // --- slab loader: one 128B K-slab (one group) of A and B ---
    auto load_slab = [&](int g, int buf) {
        unsigned dA = smem_base + buf * STAGE_AB;
        unsigned dB = dA + STAGE_A;
        const char* sAg = reinterpret_cast<const char*>(gA) + g * 128;
        const char* sBg = reinterpret_cast<const char*>(gB) + g * 128;
#pragma unroll
        for (int it = 0; it < 4; ++it) {
            int c = tid + it * 256;         // 0..1023
            int row = c >> 3, unit = c & 7;
            unsigned off = row * 128 + ((unit ^ (row & 7)) << 4);
            cp16(dA + off, sAg + (size_t)row * I_DIM + unit * 16);
            cp16(dB + off, sBg + (size_t)row * I_DIM + unit * 16);
        }
    };

    load_slab(0, 0);
    asm volatile("cp.async.commit_group;\n");
    load_slab(1, 1);
    asm volatile("cp.async.commit_group;\n");

    // per-lane ldmatrix address components
    const int selA_row = ((lane >> 3) & 1) * 8 + (lane & 7);
    const int bhA = lane >> 4;              // 0/1 : 16B half of k32
    const int selB_row = ((lane >> 4) & 1) * 8 + (lane & 7);
    const int bhB = (lane >> 3) & 1;

    float acc_f[4][4][4];
#pragma unroll
    for (int i = 0; i < 4; ++i)
#pragma unroll
        for (int j = 0; j < 4; ++j)
#pragma unroll
            for (int k = 0; k < 4; ++k) acc_f[i][j][k] = 0.f;

    __syncthreads();                        // sScale visible

    for (int g = 0; g < NGRP; ++g) {
        if (g + 2 < NGRP) {
            load_slab(g + 2, (g + 2) % 3);
            asm volatile("cp.async.commit_group;\n");
            asm volatile("cp.async.wait_group 2;\n");
        } else if (g + 1 < NGRP) {
            asm volatile("cp.async.wait_group 1;\n");
        } else {
            asm volatile("cp.async.wait_group 0;\n");
        }
        __syncthreads();                    // slab g visible

        const unsigned aBase = smem_base + (g % 3) * STAGE_AB;
        const unsigned bBase = aBase + STAGE_A;

        int acc_i[4][4][4];
#pragma unroll
        for (int i = 0; i < 4; ++i)
#pragma unroll
            for (int j = 0; j < 4; ++j)
#pragma unroll
                for (int k = 0; k < 4; ++k) acc_i[i][j][k] = 0;

#pragma unroll
        for (int kk = 0; kk < 4; ++kk) {
            unsigned a[4][4];
            unsigned b[4][2];
#pragma unroll
            for (int mt = 0; mt < 4; ++mt) {
                int row = wm * 64 + mt * 16 + selA_row;
                unsigned slot = (unsigned)((kk * 2 + bhA) ^ (row & 7));
                ldsm4(a[mt][0], a[mt][1], a[mt][2], a[mt][3],
                      aBase + row * 128 + (slot << 4));
            }
#pragma unroll
            for (int p = 0; p < 2; ++p) {   // nt pair p -> nt 2p, 2p+1
                int row = wn * 32 + p * 16 + selB_row;
                unsigned slot = (unsigned)((kk * 2 + bhB) ^ (row & 7));
                ldsm4(b[2 * p][0], b[2 * p][1], b[2 * p + 1][0], b[2 * p + 1][1],
                      bBase + row * 128 + (slot << 4));
            }
#pragma unroll
            for (int mt = 0; mt < 4; ++mt)
#pragma unroll
                for (int nt = 0; nt < 4; ++nt)
                    mma_s8(acc_i[mt][nt], a[mt], b[nt]);
        }

        // fold exact int32 group sums with per-(col,group) scale
#pragma unroll
        for (int nt = 0; nt < 4; ++nt) {
            int c0 = wn * 32 + nt * 8 + 2 * (lane & 3);
            float s0 = sScale[c0 * NGRP + g];
            float s1 = sScale[(c0 + 1) * NGRP + g];
#pragma unroll
            for (int mt = 0; mt < 4; ++mt) {
                acc_f[mt][nt][0] += s0 * (float)acc_i[mt][nt][0];
                acc_f[mt][nt][1] += s1 * (float)acc_i[mt][nt][1];
                acc_f[mt][nt][2] += s0 * (float)acc_i[mt][nt][2];
                acc_f[mt][nt][3] += s1 * (float)acc_i[mt][nt][3];
            }
        }
        __syncthreads();                    // stage reusable
    }

    // --- epilogue: out = s_act[m] * acc + bias[o] ---
#pragma unroll
    for (int mt = 0; mt < 4; ++mt) {
        int r0 = bm * 128 + wm * 64 + mt * 16 + (lane >> 2);
        float sa0 = __ldg(act_scale + (r0 & (S_LEN - 1)));
        float sa1 = __ldg(act_scale + ((r0 + 8) & (S_LEN - 1)));
#pragma unroll
        for (int nt = 0; nt < 4; ++nt) {
            int c0 = bn * 128 + wn * 32 + nt * 8 + 2 * (lane & 3);
            float b0 = __ldg(bias + c0);
            float b1 = __ldg(bias + c0 + 1);
            float2 v0, v1;
            v0.x = sa0 * acc_f[mt][nt][0] + b0;
            v0.y = sa0 * acc_f[mt][nt][1] + b1;
            v1.x = sa1 * acc_f[mt][nt][2] + b0;
            v1.y = sa1 * acc_f[mt][nt][3] + b1;
            *reinterpret_cast<float2*>(&out[(size_t)r0 * O_DIM + c0]) = v0;
            *reinterpret_cast<float2*>(&out[(size_t)(r0 + 8) * O_DIM + c0]) = v1;
        }
    }
}

// ---------------------------------------------------------------------------
// Launch. Inputs: x, qweight, act_scale, weight_scale, weight_zero, bias.
// ---------------------------------------------------------------------------
extern "C" void kernel_launch(void* const* d_in, const int* in_sizes, int n_in,
                              void* d_out, int out_size) {
    const float* x        = (const float*)d_in[0];
    const int*   qweight  = (const int*)d_in[1];
    const float* actscale = (const float*)d_in[2];
    const float* wscale   = (const float*)d_in[3];
    const int*   wzero    = (const int*)d_in[4];
    const float* bias     = (const float*)d_in[5];
    float* out = (float*)d_out;

    prep_kernel<<<40960, 256>>>(x, actscale, qweight, wzero);

    cudaFuncSetAttribute(gemm_kernel,
                         cudaFuncAttributeMaxDynamicSharedMemorySize, SMEM_TOTAL);
    dim3 grid(O_DIM / 128, M_DIM / 128);   // (32, 64); bn fastest for B-tile L2 reuse
    gemm_kernel<<<grid, 256, SMEM_TOTAL>>>(actscale, wscale, bias, out);
}